// round 11
// baseline (speedup 1.0000x reference)
#include <cuda_runtime.h>
#include <cuda_fp16.h>
#include <cstdint>

#define NN 50000
#define D  128
#define BM 128
#define EMAX 640000
#define SCAN_BLOCKS 196   // ceil(50000/256) — used for k_init grid floor

// Scratch: __device__ globals (no allocation allowed).
__device__ __align__(128) __half g_aggh[(size_t)NN * D];  // MEAN (fp16)
__device__ __align__(128) __half g_xh [(size_t)NN * D];   // x in fp16
__device__ __align__(128) __half g_h1h[(size_t)NN * D];   // h1 in fp16
__device__ __align__(128) int    g_cnt[NN];
__device__ __align__(128) int    g_rowptr[NN + 1];
__device__ __align__(128) int    g_col[EMAX];
__device__ int g_is64;

// ---------------------------------------------------------------------------
// Fused init: zero g_cnt, convert x -> fp16, block 0 probes edge dtype
// (int64 ids < 2^31 -> all odd 32-bit words zero).
// ---------------------------------------------------------------------------
__global__ void k_init(const float* __restrict__ x,
                       const int* __restrict__ ei32, int n32) {
    long long i = (long long)blockIdx.x * 256 + threadIdx.x;
    if (i < NN) g_cnt[(int)i] = 0;

    long long tot8 = (long long)NN * D / 8;
    if (i < tot8) {
        const float4* p = reinterpret_cast<const float4*>(x) + i * 2;
        float4 a = p[0], b = p[1];
        __half2 h0 = __floats2half2_rn(a.x, a.y);
        __half2 h1 = __floats2half2_rn(a.z, a.w);
        __half2 h2 = __floats2half2_rn(b.x, b.y);
        __half2 h3 = __floats2half2_rn(b.z, b.w);
        uint4 o;
        o.x = *reinterpret_cast<uint32_t*>(&h0);
        o.y = *reinterpret_cast<uint32_t*>(&h1);
        o.z = *reinterpret_cast<uint32_t*>(&h2);
        o.w = *reinterpret_cast<uint32_t*>(&h3);
        reinterpret_cast<uint4*>(g_xh)[i] = o;
    }

    if (blockIdx.x == 0) {
        __shared__ int any_nz;
        if (threadIdx.x == 0) any_nz = 0;
        __syncthreads();
        int limit = n32 < 8192 ? n32 : 8192;
        int found = 0;
        for (int k = threadIdx.x * 2 + 1; k < limit; k += 512)
            if (ei32[k] != 0) { found = 1; break; }
        if (found) atomicOr(&any_nz, 1);
        __syncthreads();
        if (threadIdx.x == 0) g_is64 = any_nz ? 0 : 1;
    }
}

// Low-word-only index read (node ids < 2^31: high word of int64 is zero).
__device__ __forceinline__ int eidx(const void* ei, int i) {
    return g_is64 ? ((const int*)ei)[2 * i] : ((const int*)ei)[i];
}

__global__ void k_hist(const void* __restrict__ ei, int E) {
    int e = blockIdx.x * blockDim.x + threadIdx.x;
    if (e < E) atomicAdd(&g_cnt[eidx(ei, E + e)], 1);
}

// ---------------------------------------------------------------------------
// Single-block exclusive scan of g_cnt[0..NN) -> g_rowptr (+cursor in g_cnt).
// 1024 threads x 49 contiguous elements each; Hillis-Steele over partials.
// ---------------------------------------------------------------------------
#define SEG 49   // ceil(50000/1024)
__global__ __launch_bounds__(1024) void k_scan(int E) {
    __shared__ int sh[1024];
    int t = threadIdx.x;
    int lo = t * SEG;
    int hi = lo + SEG < NN ? lo + SEG : NN;

    int vals[SEG];
    int s = 0;
    for (int i = lo; i < hi; i++) {
        int v = g_cnt[i];
        vals[i - lo] = v;
        s += v;
    }
    sh[t] = s;
    __syncthreads();
    for (int off = 1; off < 1024; off <<= 1) {
        int u = (t >= off) ? sh[t - off] : 0;
        __syncthreads();
        sh[t] += u;
        __syncthreads();
    }
    int base = (t > 0) ? sh[t - 1] : 0;   // exclusive prefix of this segment
    for (int i = lo; i < hi; i++) {
        g_rowptr[i] = base;
        g_cnt[i] = base;                  // cursor for fill
        base += vals[i - lo];
    }
    if (t == 0) g_rowptr[NN] = E;
}

__global__ void k_fill(const void* __restrict__ ei, int E) {
    int e = blockIdx.x * blockDim.x + threadIdx.x;
    if (e < E) {
        int s = eidx(ei, e);
        int d = eidx(ei, E + e);
        int idx = atomicAdd(&g_cnt[d], 1);
        g_col[idx] = s;
    }
}

// ---------------------------------------------------------------------------
// CSR gather over fp16 features, fp32 accumulation, fp16 mean output.
// One warp per node; half-warp h handles edges of parity h, 4 at a time with
// predicated tail -> MLP 8 per warp. shfl_xor(16) combine; lanes 0-15 write.
// ---------------------------------------------------------------------------
__global__ __launch_bounds__(256) void k_gather(int use_h1) {
    int node = blockIdx.x * 8 + (threadIdx.x >> 5);
    if (node >= NN) return;
    int lane = threadIdx.x & 31;
    int half = lane >> 4;
    int li   = lane & 15;
    const __half* f = use_h1 ? g_h1h : g_xh;
    int beg = g_rowptr[node], end = g_rowptr[node + 1];

    float acc[8];
#pragma unroll
    for (int q = 0; q < 8; q++) acc[q] = 0.f;

    if (beg < end) {
        for (int j = beg + half; j < end; j += 8) {
            int i1 = j + 2, i2 = j + 4, i3 = j + 6;
            int s0 = g_col[j];
            int s1 = g_col[i1 < end ? i1 : beg];
            int s2 = g_col[i2 < end ? i2 : beg];
            int s3 = g_col[i3 < end ? i3 : beg];
            float m1 = i1 < end ? 1.f : 0.f;
            float m2 = i2 < end ? 1.f : 0.f;
            float m3 = i3 < end ? 1.f : 0.f;
            uint4 u0 = reinterpret_cast<const uint4*>(f + (size_t)s0 * D)[li];
            uint4 u1 = reinterpret_cast<const uint4*>(f + (size_t)s1 * D)[li];
            uint4 u2 = reinterpret_cast<const uint4*>(f + (size_t)s2 * D)[li];
            uint4 u3 = reinterpret_cast<const uint4*>(f + (size_t)s3 * D)[li];
#pragma unroll
            for (int w = 0; w < 4; w++) {
                uint32_t c0 = (&u0.x)[w], c1 = (&u1.x)[w];
                uint32_t c2 = (&u2.x)[w], c3 = (&u3.x)[w];
                float2 f0 = __half22float2(*reinterpret_cast<__half2*>(&c0));
                float2 f1 = __half22float2(*reinterpret_cast<__half2*>(&c1));
                float2 f2 = __half22float2(*reinterpret_cast<__half2*>(&c2));
                float2 f3 = __half22float2(*reinterpret_cast<__half2*>(&c3));
                acc[2*w]   += f0.x + m1 * f1.x + m2 * f2.x + m3 * f3.x;
                acc[2*w+1] += f0.y + m1 * f1.y + m2 * f2.y + m3 * f3.y;
            }
        }
    }
#pragma unroll
    for (int q = 0; q < 8; q++)
        acc[q] += __shfl_xor_sync(0xffffffffu, acc[q], 16);

    if (half == 0) {
        float inv = 1.0f / fmaxf((float)(end - beg), 1.0f);
        __half2 h0 = __floats2half2_rn(acc[0]*inv, acc[1]*inv);
        __half2 h1 = __floats2half2_rn(acc[2]*inv, acc[3]*inv);
        __half2 h2 = __floats2half2_rn(acc[4]*inv, acc[5]*inv);
        __half2 h3 = __floats2half2_rn(acc[6]*inv, acc[7]*inv);
        uint4 o;
        o.x = *reinterpret_cast<uint32_t*>(&h0);
        o.y = *reinterpret_cast<uint32_t*>(&h1);
        o.z = *reinterpret_cast<uint32_t*>(&h2);
        o.w = *reinterpret_cast<uint32_t*>(&h3);
        *reinterpret_cast<uint4*>(&g_aggh[(size_t)node * D + li * 8]) = o;
    }
}

// ---------------------------------------------------------------------------
// tf32 tensor-core fused SAGE GEMM:
//   out = relu( mean @ Wl + feat @ Wr + b ),  A = [g_aggh | feat] (both fp16)
// BM=128, BN=128, BK=32, 8 warps, warp tile 64x32; SMEM stride 36
// (bank = (4*grp+tig)%32, conflict-free).
// ---------------------------------------------------------------------------
__device__ __forceinline__ uint32_t to_tf32(float f) {
    uint32_t r;
    asm("cvt.rna.tf32.f32 %0, %1;" : "=r"(r) : "f"(f));
    return r;
}

__global__ __launch_bounds__(256) void k_gemm(
    const float* __restrict__ Wl,
    const float* __restrict__ Wr,
    const float* __restrict__ bias,
    float* __restrict__ outbuf,
    int in_from_h1, int out_to_h1)
{
    __shared__ uint32_t As[128][36];
    __shared__ uint32_t Bs[128][36];

    const int tid  = threadIdx.x;
    const int wid  = tid >> 5;
    const int lane = tid & 31;
    const int grp  = lane >> 2;
    const int tig  = lane & 3;
    const int warpRow = (wid >> 2) * 64;
    const int warpCol = (wid & 3) * 32;
    const int rowBase = blockIdx.x * BM;
    const __half* xh = in_from_h1 ? g_h1h : g_xh;

    float acc[4][4][4];
#pragma unroll
    for (int mt = 0; mt < 4; mt++)
#pragma unroll
        for (int nt = 0; nt < 4; nt++)
#pragma unroll
            for (int q = 0; q < 4; q++) acc[mt][nt][q] = 0.f;

    const int arow  = tid >> 1;
    const int akloc = (tid & 1) * 16;

    for (int kb = 0; kb < 8; kb++) {
        const int k0 = kb * 32;

        // ---- stage A: both K-halves are fp16 now (uniform path)
        {
            int grow = rowBase + arow;
            uint2* dstp = reinterpret_cast<uint2*>(&As[arow][akloc]);
            if (grow < NN) {
                int kg = k0 + akloc;
                const __half* srcp = (k0 < D)
                    ? &g_aggh[(size_t)grow * D + kg]
                    : &xh[(size_t)grow * D + (kg - D)];
                const uint4* p = reinterpret_cast<const uint4*>(srcp);
#pragma unroll
                for (int q = 0; q < 2; q++) {
                    uint4 u = p[q];
#pragma unroll
                    for (int w = 0; w < 4; w++) {
                        uint32_t c = (&u.x)[w];
                        float2 fv = __half22float2(*reinterpret_cast<__half2*>(&c));
                        dstp[4*q + w] = make_uint2(to_tf32(fv.x), to_tf32(fv.y));
                    }
                }
            } else {
#pragma unroll
                for (int q = 0; q < 8; q++) dstp[q] = make_uint2(0u, 0u);
            }
        }

        // ---- stage B transposed: Bs[col][k] from W[k][col]
#pragma unroll
        for (int it = 0; it < 4; it++) {
            int lin = tid + it * 256;
            int kk  = lin >> 5;
            int c4  = (lin & 31) * 4;
            int kg  = k0 + kk;
            const float* wsrc = (kg < D) ? (Wl + (size_t)kg * D + c4)
                                         : (Wr + (size_t)(kg - D) * D + c4);
            float4 u = *reinterpret_cast<const float4*>(wsrc);
            Bs[c4 + 0][kk] = to_tf32(u.x);
            Bs[c4 + 1][kk] = to_tf32(u.y);
            Bs[c4 + 2][kk] = to_tf32(u.z);
            Bs[c4 + 3][kk] = to_tf32(u.w);
        }
        __syncthreads();

#pragma unroll
        for (int ks = 0; ks < 4; ks++) {
            const int kb8 = ks * 8;
            uint32_t a[4][4], b[4][2];
#pragma unroll
            for (int mt = 0; mt < 4; mt++) {
                int r0 = warpRow + mt * 16;
                a[mt][0] = As[r0 + grp    ][kb8 + tig];
                a[mt][1] = As[r0 + grp + 8][kb8 + tig];
                a[mt][2] = As[r0 + grp    ][kb8 + tig + 4];
                a[mt][3] = As[r0 + grp + 8][kb8 + tig + 4];
            }
#pragma unroll
            for (int nt = 0; nt < 4; nt++) {
                int cn = warpCol + nt * 8 + grp;
                b[nt][0] = Bs[cn][kb8 + tig];
                b[nt][1] = Bs[cn][kb8 + tig + 4];
            }
#pragma unroll
            for (int mt = 0; mt < 4; mt++)
#pragma unroll
                for (int nt = 0; nt < 4; nt++) {
                    asm volatile(
                        "mma.sync.aligned.m16n8k8.row.col.f32.tf32.tf32.f32 "
                        "{%0,%1,%2,%3}, {%4,%5,%6,%7}, {%8,%9}, {%0,%1,%2,%3};\n"
                        : "+f"(acc[mt][nt][0]), "+f"(acc[mt][nt][1]),
                          "+f"(acc[mt][nt][2]), "+f"(acc[mt][nt][3])
                        : "r"(a[mt][0]), "r"(a[mt][1]), "r"(a[mt][2]), "r"(a[mt][3]),
                          "r"(b[nt][0]), "r"(b[nt][1]));
                }
        }
        __syncthreads();
    }

    // ---- epilogue
#pragma unroll
    for (int nt = 0; nt < 4; nt++) {
        int c = warpCol + nt * 8 + 2 * tig;
        float b0 = bias[c], b1 = bias[c + 1];
#pragma unroll
        for (int mt = 0; mt < 4; mt++) {
            int r = rowBase + warpRow + mt * 16 + grp;
            float v0 = fmaxf(acc[mt][nt][0] + b0, 0.f);
            float v1 = fmaxf(acc[mt][nt][1] + b1, 0.f);
            float v2 = fmaxf(acc[mt][nt][2] + b0, 0.f);
            float v3 = fmaxf(acc[mt][nt][3] + b1, 0.f);
            if (out_to_h1) {
                if (r < NN)
                    *reinterpret_cast<__half2*>(&g_h1h[(size_t)r * D + c]) =
                        __floats2half2_rn(v0, v1);
                if (r + 8 < NN)
                    *reinterpret_cast<__half2*>(&g_h1h[(size_t)(r + 8) * D + c]) =
                        __floats2half2_rn(v2, v3);
            } else {
                if (r < NN)
                    *reinterpret_cast<float2*>(&outbuf[(size_t)r * D + c]) =
                        make_float2(v0, v1);
                if (r + 8 < NN)
                    *reinterpret_cast<float2*>(&outbuf[(size_t)(r + 8) * D + c]) =
                        make_float2(v2, v3);
            }
        }
    }
}

// ---------------------------------------------------------------------------
extern "C" void kernel_launch(void* const* d_in, const int* in_sizes, int n_in,
                              void* d_out, int out_size) {
    const float* x   = (const float*)d_in[0];
    const void*  ei  = d_in[1];
    const float* W1l = (const float*)d_in[2];
    const float* b1  = (const float*)d_in[3];
    const float* W1r = (const float*)d_in[4];
    const float* W2l = (const float*)d_in[5];
    const float* b2  = (const float*)d_in[6];
    const float* W2r = (const float*)d_in[7];
    float*       out = (float*)d_out;

    const int E = in_sizes[1] / 2;
    const int eblocks = (E + 255) / 256;
    const int gemmBlocks = (NN + BM - 1) / BM;
    const int gatherBlocks = (NN + 7) / 8;
    const int initBlocks = (int)(((long long)NN * D / 8 + 255) / 256);

    k_init<<<initBlocks, 256>>>(x, (const int*)ei, in_sizes[1]);

    // CSR build
    k_hist<<<eblocks, 256>>>(ei, E);
    k_scan<<<1, 1024>>>(E);
    k_fill<<<eblocks, 256>>>(ei, E);

    // Layer 1
    k_gather<<<gatherBlocks, 256>>>(0);
    k_gemm<<<gemmBlocks, 256>>>(W1l, W1r, b1, out, 0, 1);   // -> g_h1h (fp16)

    // Layer 2
    k_gather<<<gatherBlocks, 256>>>(1);
    k_gemm<<<gemmBlocks, 256>>>(W2l, W2r, b2, out, 1, 0);   // -> d_out
}

// round 12
// speedup vs baseline: 1.3270x; 1.3270x over previous
#include <cuda_runtime.h>
#include <cuda_fp16.h>
#include <cstdint>

#define NN 50000
#define D  128
#define BM 128
#define EMAX 640000
#define SCAN_BLOCKS 196   // ceil(50000/256)

// Scratch: __device__ globals (no allocation allowed).
__device__ __align__(128) __half g_aggh[(size_t)NN * D];  // MEAN (fp16)
__device__ __align__(128) __half g_xh [(size_t)NN * D];   // x in fp16
__device__ __align__(128) __half g_h1h[(size_t)NN * D];   // h1 in fp16
__device__ __align__(128) int    g_cnt[NN];
__device__ __align__(128) int    g_rowptr[NN + 1];
__device__ __align__(128) int    g_col[EMAX];
__device__ __align__(128) int    g_bsum[256];
__device__ int g_is64;

// ---------------------------------------------------------------------------
// Fused init: zero g_cnt, convert x -> fp16, block 0 probes edge dtype
// (int64 ids < 2^31 -> all odd 32-bit words zero).
// ---------------------------------------------------------------------------
__global__ void k_init(const float* __restrict__ x,
                       const int* __restrict__ ei32, int n32) {
    long long i = (long long)blockIdx.x * 256 + threadIdx.x;
    if (i < NN) g_cnt[(int)i] = 0;

    long long tot8 = (long long)NN * D / 8;
    if (i < tot8) {
        const float4* p = reinterpret_cast<const float4*>(x) + i * 2;
        float4 a = p[0], b = p[1];
        __half2 h0 = __floats2half2_rn(a.x, a.y);
        __half2 h1 = __floats2half2_rn(a.z, a.w);
        __half2 h2 = __floats2half2_rn(b.x, b.y);
        __half2 h3 = __floats2half2_rn(b.z, b.w);
        uint4 o;
        o.x = *reinterpret_cast<uint32_t*>(&h0);
        o.y = *reinterpret_cast<uint32_t*>(&h1);
        o.z = *reinterpret_cast<uint32_t*>(&h2);
        o.w = *reinterpret_cast<uint32_t*>(&h3);
        reinterpret_cast<uint4*>(g_xh)[i] = o;
    }

    if (blockIdx.x == 0) {
        __shared__ int any_nz;
        if (threadIdx.x == 0) any_nz = 0;
        __syncthreads();
        int limit = n32 < 8192 ? n32 : 8192;
        int found = 0;
        for (int k = threadIdx.x * 2 + 1; k < limit; k += 512)
            if (ei32[k] != 0) { found = 1; break; }
        if (found) atomicOr(&any_nz, 1);
        __syncthreads();
        if (threadIdx.x == 0) g_is64 = any_nz ? 0 : 1;
    }
}

// Low-word-only index read (node ids < 2^31: high word of int64 is zero).
__device__ __forceinline__ int eidx(const void* ei, int i) {
    return g_is64 ? ((const int*)ei)[2 * i] : ((const int*)ei)[i];
}

__global__ void k_hist(const void* __restrict__ ei, int E) {
    int e = blockIdx.x * blockDim.x + threadIdx.x;
    if (e < E) atomicAdd(&g_cnt[eidx(ei, E + e)], 1);
}

// Stage 1: per-block exclusive scan, publish block sums. (R9 version)
__global__ void k_scan1() {
    __shared__ int sh[256];
    int gid = blockIdx.x * 256 + threadIdx.x;
    int v = (gid < NN) ? g_cnt[gid] : 0;
    sh[threadIdx.x] = v;
    __syncthreads();
    for (int off = 1; off < 256; off <<= 1) {
        int t = (threadIdx.x >= off) ? sh[threadIdx.x - off] : 0;
        __syncthreads();
        sh[threadIdx.x] += t;
        __syncthreads();
    }
    if (gid < NN) g_rowptr[gid] = sh[threadIdx.x] - v;
    if (threadIdx.x == 255) g_bsum[blockIdx.x] = sh[255];
}

// Stage 2: each block reduces preceding block sums and applies offset.
__global__ void k_scan3(int E) {
    __shared__ int sh[256];
    int t = threadIdx.x;
    sh[t] = (t < blockIdx.x) ? g_bsum[t] : 0;
    __syncthreads();
    for (int off = 128; off > 0; off >>= 1) {
        if (t < off) sh[t] += sh[t + off];
        __syncthreads();
    }
    int base = sh[0];
    int gid = blockIdx.x * 256 + t;
    if (gid < NN) {
        int r = g_rowptr[gid] + base;
        g_rowptr[gid] = r;
        g_cnt[gid] = r;          // cursor for fill
    }
    if (gid == 0) g_rowptr[NN] = E;
}

__global__ void k_fill(const void* __restrict__ ei, int E) {
    int e = blockIdx.x * blockDim.x + threadIdx.x;
    if (e < E) {
        int s = eidx(ei, e);
        int d = eidx(ei, E + e);
        int idx = atomicAdd(&g_cnt[d], 1);
        g_col[idx] = s;
    }
}

// ---------------------------------------------------------------------------
// CSR gather over fp16 features, fp32 accumulation, fp16 mean output.
// One warp per node; half-warp h handles edges of parity h, 4 at a time with
// predicated tail -> MLP 8 per warp. shfl_xor(16) combine; lanes 0-15 write.
// ---------------------------------------------------------------------------
__global__ __launch_bounds__(256) void k_gather(int use_h1) {
    int node = blockIdx.x * 8 + (threadIdx.x >> 5);
    if (node >= NN) return;
    int lane = threadIdx.x & 31;
    int half = lane >> 4;
    int li   = lane & 15;
    const __half* f = use_h1 ? g_h1h : g_xh;
    int beg = g_rowptr[node], end = g_rowptr[node + 1];

    float acc[8];
#pragma unroll
    for (int q = 0; q < 8; q++) acc[q] = 0.f;

    if (beg < end) {
        for (int j = beg + half; j < end; j += 8) {
            int i1 = j + 2, i2 = j + 4, i3 = j + 6;
            int s0 = g_col[j];
            int s1 = g_col[i1 < end ? i1 : beg];
            int s2 = g_col[i2 < end ? i2 : beg];
            int s3 = g_col[i3 < end ? i3 : beg];
            float m1 = i1 < end ? 1.f : 0.f;
            float m2 = i2 < end ? 1.f : 0.f;
            float m3 = i3 < end ? 1.f : 0.f;
            uint4 u0 = reinterpret_cast<const uint4*>(f + (size_t)s0 * D)[li];
            uint4 u1 = reinterpret_cast<const uint4*>(f + (size_t)s1 * D)[li];
            uint4 u2 = reinterpret_cast<const uint4*>(f + (size_t)s2 * D)[li];
            uint4 u3 = reinterpret_cast<const uint4*>(f + (size_t)s3 * D)[li];
#pragma unroll
            for (int w = 0; w < 4; w++) {
                uint32_t c0 = (&u0.x)[w], c1 = (&u1.x)[w];
                uint32_t c2 = (&u2.x)[w], c3 = (&u3.x)[w];
                float2 f0 = __half22float2(*reinterpret_cast<__half2*>(&c0));
                float2 f1 = __half22float2(*reinterpret_cast<__half2*>(&c1));
                float2 f2 = __half22float2(*reinterpret_cast<__half2*>(&c2));
                float2 f3 = __half22float2(*reinterpret_cast<__half2*>(&c3));
                acc[2*w]   += f0.x + m1 * f1.x + m2 * f2.x + m3 * f3.x;
                acc[2*w+1] += f0.y + m1 * f1.y + m2 * f2.y + m3 * f3.y;
            }
        }
    }
#pragma unroll
    for (int q = 0; q < 8; q++)
        acc[q] += __shfl_xor_sync(0xffffffffu, acc[q], 16);

    if (half == 0) {
        float inv = 1.0f / fmaxf((float)(end - beg), 1.0f);
        __half2 h0 = __floats2half2_rn(acc[0]*inv, acc[1]*inv);
        __half2 h1 = __floats2half2_rn(acc[2]*inv, acc[3]*inv);
        __half2 h2 = __floats2half2_rn(acc[4]*inv, acc[5]*inv);
        __half2 h3 = __floats2half2_rn(acc[6]*inv, acc[7]*inv);
        uint4 o;
        o.x = *reinterpret_cast<uint32_t*>(&h0);
        o.y = *reinterpret_cast<uint32_t*>(&h1);
        o.z = *reinterpret_cast<uint32_t*>(&h2);
        o.w = *reinterpret_cast<uint32_t*>(&h3);
        *reinterpret_cast<uint4*>(&g_aggh[(size_t)node * D + li * 8]) = o;
    }
}

// ---------------------------------------------------------------------------
// tf32 tensor-core fused SAGE GEMM:
//   out = relu( mean @ Wl + feat @ Wr + b ),  A = [g_aggh | feat] (both fp16)
// BM=128, BN=128, BK=32, 8 warps, warp tile 64x32; SMEM stride 36.
// ---------------------------------------------------------------------------
__device__ __forceinline__ uint32_t to_tf32(float f) {
    uint32_t r;
    asm("cvt.rna.tf32.f32 %0, %1;" : "=r"(r) : "f"(f));
    return r;
}

__global__ __launch_bounds__(256) void k_gemm(
    const float* __restrict__ Wl,
    const float* __restrict__ Wr,
    const float* __restrict__ bias,
    float* __restrict__ outbuf,
    int in_from_h1, int out_to_h1)
{
    __shared__ uint32_t As[128][36];
    __shared__ uint32_t Bs[128][36];

    const int tid  = threadIdx.x;
    const int wid  = tid >> 5;
    const int lane = tid & 31;
    const int grp  = lane >> 2;
    const int tig  = lane & 3;
    const int warpRow = (wid >> 2) * 64;
    const int warpCol = (wid & 3) * 32;
    const int rowBase = blockIdx.x * BM;
    const __half* xh = in_from_h1 ? g_h1h : g_xh;

    float acc[4][4][4];
#pragma unroll
    for (int mt = 0; mt < 4; mt++)
#pragma unroll
        for (int nt = 0; nt < 4; nt++)
#pragma unroll
            for (int q = 0; q < 4; q++) acc[mt][nt][q] = 0.f;

    const int arow  = tid >> 1;
    const int akloc = (tid & 1) * 16;

    for (int kb = 0; kb < 8; kb++) {
        const int k0 = kb * 32;

        // ---- stage A: both K-halves fp16 (uniform path)
        {
            int grow = rowBase + arow;
            uint2* dstp = reinterpret_cast<uint2*>(&As[arow][akloc]);
            if (grow < NN) {
                int kg = k0 + akloc;
                const __half* srcp = (k0 < D)
                    ? &g_aggh[(size_t)grow * D + kg]
                    : &xh[(size_t)grow * D + (kg - D)];
                const uint4* p = reinterpret_cast<const uint4*>(srcp);
#pragma unroll
                for (int q = 0; q < 2; q++) {
                    uint4 u = p[q];
#pragma unroll
                    for (int w = 0; w < 4; w++) {
                        uint32_t c = (&u.x)[w];
                        float2 fv = __half22float2(*reinterpret_cast<__half2*>(&c));
                        dstp[4*q + w] = make_uint2(to_tf32(fv.x), to_tf32(fv.y));
                    }
                }
            } else {
#pragma unroll
                for (int q = 0; q < 8; q++) dstp[q] = make_uint2(0u, 0u);
            }
        }

        // ---- stage B transposed: Bs[col][k] from W[k][col]
#pragma unroll
        for (int it = 0; it < 4; it++) {
            int lin = tid + it * 256;
            int kk  = lin >> 5;
            int c4  = (lin & 31) * 4;
            int kg  = k0 + kk;
            const float* wsrc = (kg < D) ? (Wl + (size_t)kg * D + c4)
                                         : (Wr + (size_t)(kg - D) * D + c4);
            float4 u = *reinterpret_cast<const float4*>(wsrc);
            Bs[c4 + 0][kk] = to_tf32(u.x);
            Bs[c4 + 1][kk] = to_tf32(u.y);
            Bs[c4 + 2][kk] = to_tf32(u.z);
            Bs[c4 + 3][kk] = to_tf32(u.w);
        }
        __syncthreads();

#pragma unroll
        for (int ks = 0; ks < 4; ks++) {
            const int kb8 = ks * 8;
            uint32_t a[4][4], b[4][2];
#pragma unroll
            for (int mt = 0; mt < 4; mt++) {
                int r0 = warpRow + mt * 16;
                a[mt][0] = As[r0 + grp    ][kb8 + tig];
                a[mt][1] = As[r0 + grp + 8][kb8 + tig];
                a[mt][2] = As[r0 + grp    ][kb8 + tig + 4];
                a[mt][3] = As[r0 + grp + 8][kb8 + tig + 4];
            }
#pragma unroll
            for (int nt = 0; nt < 4; nt++) {
                int cn = warpCol + nt * 8 + grp;
                b[nt][0] = Bs[cn][kb8 + tig];
                b[nt][1] = Bs[cn][kb8 + tig + 4];
            }
#pragma unroll
            for (int mt = 0; mt < 4; mt++)
#pragma unroll
                for (int nt = 0; nt < 4; nt++) {
                    asm volatile(
                        "mma.sync.aligned.m16n8k8.row.col.f32.tf32.tf32.f32 "
                        "{%0,%1,%2,%3}, {%4,%5,%6,%7}, {%8,%9}, {%0,%1,%2,%3};\n"
                        : "+f"(acc[mt][nt][0]), "+f"(acc[mt][nt][1]),
                          "+f"(acc[mt][nt][2]), "+f"(acc[mt][nt][3])
                        : "r"(a[mt][0]), "r"(a[mt][1]), "r"(a[mt][2]), "r"(a[mt][3]),
                          "r"(b[nt][0]), "r"(b[nt][1]));
                }
        }
        __syncthreads();
    }

    // ---- epilogue
#pragma unroll
    for (int nt = 0; nt < 4; nt++) {
        int c = warpCol + nt * 8 + 2 * tig;
        float b0 = bias[c], b1 = bias[c + 1];
#pragma unroll
        for (int mt = 0; mt < 4; mt++) {
            int r = rowBase + warpRow + mt * 16 + grp;
            float v0 = fmaxf(acc[mt][nt][0] + b0, 0.f);
            float v1 = fmaxf(acc[mt][nt][1] + b1, 0.f);
            float v2 = fmaxf(acc[mt][nt][2] + b0, 0.f);
            float v3 = fmaxf(acc[mt][nt][3] + b1, 0.f);
            if (out_to_h1) {
                if (r < NN)
                    *reinterpret_cast<__half2*>(&g_h1h[(size_t)r * D + c]) =
                        __floats2half2_rn(v0, v1);
                if (r + 8 < NN)
                    *reinterpret_cast<__half2*>(&g_h1h[(size_t)(r + 8) * D + c]) =
                        __floats2half2_rn(v2, v3);
            } else {
                if (r < NN)
                    *reinterpret_cast<float2*>(&outbuf[(size_t)r * D + c]) =
                        make_float2(v0, v1);
                if (r + 8 < NN)
                    *reinterpret_cast<float2*>(&outbuf[(size_t)(r + 8) * D + c]) =
                        make_float2(v2, v3);
            }
        }
    }
}

// ---------------------------------------------------------------------------
extern "C" void kernel_launch(void* const* d_in, const int* in_sizes, int n_in,
                              void* d_out, int out_size) {
    const float* x   = (const float*)d_in[0];
    const void*  ei  = d_in[1];
    const float* W1l = (const float*)d_in[2];
    const float* b1  = (const float*)d_in[3];
    const float* W1r = (const float*)d_in[4];
    const float* W2l = (const float*)d_in[5];
    const float* b2  = (const float*)d_in[6];
    const float* W2r = (const float*)d_in[7];
    float*       out = (float*)d_out;

    const int E = in_sizes[1] / 2;
    const int eblocks = (E + 255) / 256;
    const int gemmBlocks = (NN + BM - 1) / BM;
    const int gatherBlocks = (NN + 7) / 8;
    const int initBlocks = (int)(((long long)NN * D / 8 + 255) / 256);

    k_init<<<initBlocks, 256>>>(x, (const int*)ei, in_sizes[1]);

    // CSR build (R9 two-stage scan)
    k_hist<<<eblocks, 256>>>(ei, E);
    k_scan1<<<SCAN_BLOCKS, 256>>>();
    k_scan3<<<SCAN_BLOCKS, 256>>>(E);
    k_fill<<<eblocks, 256>>>(ei, E);

    // Layer 1
    k_gather<<<gatherBlocks, 256>>>(0);
    k_gemm<<<gemmBlocks, 256>>>(W1l, W1r, b1, out, 0, 1);   // -> g_h1h (fp16)

    // Layer 2
    k_gather<<<gatherBlocks, 256>>>(1);
    k_gemm<<<gemmBlocks, 256>>>(W2l, W2r, b2, out, 1, 0);   // -> d_out
}

// round 13
// speedup vs baseline: 2.1803x; 1.6430x over previous
#include <cuda_runtime.h>
#include <cuda_fp16.h>
#include <cstdint>

#define NN 50000
#define D  128
#define BM 128
#define EMAX 640000
#define SCAN_BLOCKS 196   // ceil(50000/256)

// Scratch: __device__ globals (no allocation allowed).
__device__ __align__(128) __half g_aggh[(size_t)NN * D];  // MEAN (fp16)
__device__ __align__(128) __half g_xh [(size_t)NN * D];   // x in fp16
__device__ __align__(128) __half g_h1h[(size_t)NN * D];   // h1 in fp16
__device__ __align__(128) __half g_w1t[128 * 256];        // layer1 W^T fp16 [c][k]
__device__ __align__(128) __half g_w2t[128 * 256];        // layer2 W^T fp16 [c][k]
__device__ __align__(128) int    g_cnt[NN];
__device__ __align__(128) int    g_rowptr[NN + 1];
__device__ __align__(128) int    g_col[EMAX];
__device__ __align__(128) int    g_bsum[256];
__device__ int g_is64;

// ---------------------------------------------------------------------------
// Fused init: zero g_cnt, convert x -> fp16, transpose+convert weights to
// fp16 [c][k] (k = [Wl rows | Wr rows]), block 0 probes edge dtype.
// ---------------------------------------------------------------------------
__global__ void k_init(const float* __restrict__ x,
                       const int* __restrict__ ei32, int n32,
                       const float* __restrict__ W1l, const float* __restrict__ W1r,
                       const float* __restrict__ W2l, const float* __restrict__ W2r) {
    long long i = (long long)blockIdx.x * 256 + threadIdx.x;
    if (i < NN) g_cnt[(int)i] = 0;

    long long tot8 = (long long)NN * D / 8;
    if (i < tot8) {
        const float4* p = reinterpret_cast<const float4*>(x) + i * 2;
        float4 a = p[0], b = p[1];
        __half2 h0 = __floats2half2_rn(a.x, a.y);
        __half2 h1 = __floats2half2_rn(a.z, a.w);
        __half2 h2 = __floats2half2_rn(b.x, b.y);
        __half2 h3 = __floats2half2_rn(b.z, b.w);
        uint4 o;
        o.x = *reinterpret_cast<uint32_t*>(&h0);
        o.y = *reinterpret_cast<uint32_t*>(&h1);
        o.z = *reinterpret_cast<uint32_t*>(&h2);
        o.w = *reinterpret_cast<uint32_t*>(&h3);
        reinterpret_cast<uint4*>(g_xh)[i] = o;
    }

    // Weight transpose: 4096 threads, each does one (layer, c, 16-k group).
    if (i < 4096) {
        int layer = (int)(i >> 11);
        int rem   = (int)(i & 2047);
        int c  = rem >> 4;
        int kg = (rem & 15) * 16;
        const float* Wl = layer ? W2l : W1l;
        const float* Wr = layer ? W2r : W1r;
        __half* dst = layer ? g_w2t : g_w1t;
#pragma unroll
        for (int q = 0; q < 16; q += 2) {
            int k0 = kg + q, k1 = kg + q + 1;
            float v0 = (k0 < 128) ? Wl[k0 * 128 + c] : Wr[(k0 - 128) * 128 + c];
            float v1 = (k1 < 128) ? Wl[k1 * 128 + c] : Wr[(k1 - 128) * 128 + c];
            *reinterpret_cast<__half2*>(&dst[c * 256 + kg + q]) =
                __floats2half2_rn(v0, v1);
        }
    }

    if (blockIdx.x == 0) {
        __shared__ int any_nz;
        if (threadIdx.x == 0) any_nz = 0;
        __syncthreads();
        int limit = n32 < 8192 ? n32 : 8192;
        int found = 0;
        for (int k = threadIdx.x * 2 + 1; k < limit; k += 512)
            if (ei32[k] != 0) { found = 1; break; }
        if (found) atomicOr(&any_nz, 1);
        __syncthreads();
        if (threadIdx.x == 0) g_is64 = any_nz ? 0 : 1;
    }
}

// Low-word-only index read (node ids < 2^31: high word of int64 is zero).
__device__ __forceinline__ int eidx(const void* ei, int i) {
    return g_is64 ? ((const int*)ei)[2 * i] : ((const int*)ei)[i];
}

__global__ void k_hist(const void* __restrict__ ei, int E) {
    int e = blockIdx.x * blockDim.x + threadIdx.x;
    if (e < E) atomicAdd(&g_cnt[eidx(ei, E + e)], 1);
}

__global__ void k_scan1() {
    __shared__ int sh[256];
    int gid = blockIdx.x * 256 + threadIdx.x;
    int v = (gid < NN) ? g_cnt[gid] : 0;
    sh[threadIdx.x] = v;
    __syncthreads();
    for (int off = 1; off < 256; off <<= 1) {
        int t = (threadIdx.x >= off) ? sh[threadIdx.x - off] : 0;
        __syncthreads();
        sh[threadIdx.x] += t;
        __syncthreads();
    }
    if (gid < NN) g_rowptr[gid] = sh[threadIdx.x] - v;
    if (threadIdx.x == 255) g_bsum[blockIdx.x] = sh[255];
}

__global__ void k_scan3(int E) {
    __shared__ int sh[256];
    int t = threadIdx.x;
    sh[t] = (t < blockIdx.x) ? g_bsum[t] : 0;
    __syncthreads();
    for (int off = 128; off > 0; off >>= 1) {
        if (t < off) sh[t] += sh[t + off];
        __syncthreads();
    }
    int base = sh[0];
    int gid = blockIdx.x * 256 + t;
    if (gid < NN) {
        int r = g_rowptr[gid] + base;
        g_rowptr[gid] = r;
        g_cnt[gid] = r;          // cursor for fill
    }
    if (gid == 0) g_rowptr[NN] = E;
}

__global__ void k_fill(const void* __restrict__ ei, int E) {
    int e = blockIdx.x * blockDim.x + threadIdx.x;
    if (e < E) {
        int s = eidx(ei, e);
        int d = eidx(ei, E + e);
        int idx = atomicAdd(&g_cnt[d], 1);
        g_col[idx] = s;
    }
}

// ---------------------------------------------------------------------------
// CSR gather over fp16 features, fp32 accumulation, fp16 mean output.
// One warp per node; half-warp h handles edges of parity h, 4 at a time with
// predicated tail -> MLP 8 per warp. shfl_xor(16) combine; lanes 0-15 write.
// ---------------------------------------------------------------------------
__global__ __launch_bounds__(256) void k_gather(int use_h1) {
    int node = blockIdx.x * 8 + (threadIdx.x >> 5);
    if (node >= NN) return;
    int lane = threadIdx.x & 31;
    int half = lane >> 4;
    int li   = lane & 15;
    const __half* f = use_h1 ? g_h1h : g_xh;
    int beg = g_rowptr[node], end = g_rowptr[node + 1];

    float acc[8];
#pragma unroll
    for (int q = 0; q < 8; q++) acc[q] = 0.f;

    if (beg < end) {
        for (int j = beg + half; j < end; j += 8) {
            int i1 = j + 2, i2 = j + 4, i3 = j + 6;
            int s0 = g_col[j];
            int s1 = g_col[i1 < end ? i1 : beg];
            int s2 = g_col[i2 < end ? i2 : beg];
            int s3 = g_col[i3 < end ? i3 : beg];
            float m1 = i1 < end ? 1.f : 0.f;
            float m2 = i2 < end ? 1.f : 0.f;
            float m3 = i3 < end ? 1.f : 0.f;
            uint4 u0 = reinterpret_cast<const uint4*>(f + (size_t)s0 * D)[li];
            uint4 u1 = reinterpret_cast<const uint4*>(f + (size_t)s1 * D)[li];
            uint4 u2 = reinterpret_cast<const uint4*>(f + (size_t)s2 * D)[li];
            uint4 u3 = reinterpret_cast<const uint4*>(f + (size_t)s3 * D)[li];
#pragma unroll
            for (int w = 0; w < 4; w++) {
                uint32_t c0 = (&u0.x)[w], c1 = (&u1.x)[w];
                uint32_t c2 = (&u2.x)[w], c3 = (&u3.x)[w];
                float2 f0 = __half22float2(*reinterpret_cast<__half2*>(&c0));
                float2 f1 = __half22float2(*reinterpret_cast<__half2*>(&c1));
                float2 f2 = __half22float2(*reinterpret_cast<__half2*>(&c2));
                float2 f3 = __half22float2(*reinterpret_cast<__half2*>(&c3));
                acc[2*w]   += f0.x + m1 * f1.x + m2 * f2.x + m3 * f3.x;
                acc[2*w+1] += f0.y + m1 * f1.y + m2 * f2.y + m3 * f3.y;
            }
        }
    }
#pragma unroll
    for (int q = 0; q < 8; q++)
        acc[q] += __shfl_xor_sync(0xffffffffu, acc[q], 16);

    if (half == 0) {
        float inv = 1.0f / fmaxf((float)(end - beg), 1.0f);
        __half2 h0 = __floats2half2_rn(acc[0]*inv, acc[1]*inv);
        __half2 h1 = __floats2half2_rn(acc[2]*inv, acc[3]*inv);
        __half2 h2 = __floats2half2_rn(acc[4]*inv, acc[5]*inv);
        __half2 h3 = __floats2half2_rn(acc[6]*inv, acc[7]*inv);
        uint4 o;
        o.x = *reinterpret_cast<uint32_t*>(&h0);
        o.y = *reinterpret_cast<uint32_t*>(&h1);
        o.z = *reinterpret_cast<uint32_t*>(&h2);
        o.w = *reinterpret_cast<uint32_t*>(&h3);
        *reinterpret_cast<uint4*>(&g_aggh[(size_t)node * D + li * 8]) = o;
    }
}

// ---------------------------------------------------------------------------
// fp16 m16n8k16 tensor-core fused SAGE GEMM:
//   out = relu( mean @ Wl + feat @ Wr + b )
// A = [g_aggh | feat] (fp16), B = pre-transposed fp16 weights g_wt[c][k].
// BM=128, BN=128, BK=64 (4 stages, 8 syncs), 8 warps, warp tile 64x32.
// SMEM panels [128][72] halves, stride 36 words: fragment word index
// row*36 + tig (+4) -> bank (4*grp+tig)%32, conflict-free.
// ---------------------------------------------------------------------------
__global__ __launch_bounds__(256) void k_gemm(
    const float* __restrict__ bias,
    float* __restrict__ outbuf,
    int in_from_h1, int out_to_h1)
{
    __shared__ __align__(16) __half As[128][72];
    __shared__ __align__(16) __half Bs[128][72];

    const int tid  = threadIdx.x;
    const int wid  = tid >> 5;
    const int lane = tid & 31;
    const int grp  = lane >> 2;
    const int tig  = lane & 3;
    const int warpRow = (wid >> 2) * 64;
    const int warpCol = (wid & 3) * 32;
    const int rowBase = blockIdx.x * BM;
    const __half* xh = in_from_h1 ? g_h1h : g_xh;
    const __half* wt = in_from_h1 ? g_w2t : g_w1t;

    float acc[4][4][4];
#pragma unroll
    for (int mt = 0; mt < 4; mt++)
#pragma unroll
        for (int nt = 0; nt < 4; nt++)
#pragma unroll
            for (int q = 0; q < 4; q++) acc[mt][nt][q] = 0.f;

    const int srow  = tid >> 1;          // staging row/col (2 threads each)
    const int hbase = (tid & 1) * 32;    // 32 halves per thread = 4 uint4

    for (int kb = 0; kb < 4; kb++) {
        // ---- stage A: rows from g_aggh (kb<2) or feat (kb>=2), 64-k chunk
        {
            const __half* asrc = (kb < 2) ? g_aggh : xh;
            int koff = (kb & 1) * 64;
            int grow = rowBase + srow;
            uint4* d = reinterpret_cast<uint4*>(&As[srow][hbase]);
            if (grow < NN) {
                const uint4* s = reinterpret_cast<const uint4*>(
                    &asrc[(size_t)grow * D + koff + hbase]);
#pragma unroll
                for (int q = 0; q < 4; q++) d[q] = s[q];
            } else {
#pragma unroll
                for (int q = 0; q < 4; q++) d[q] = make_uint4(0u,0u,0u,0u);
            }
        }
        // ---- stage B: Bs[c][k] from pre-transposed fp16 weights
        {
            const uint4* s = reinterpret_cast<const uint4*>(
                &wt[srow * 256 + kb * 64 + hbase]);
            uint4* d = reinterpret_cast<uint4*>(&Bs[srow][hbase]);
#pragma unroll
            for (int q = 0; q < 4; q++) d[q] = s[q];
        }
        __syncthreads();

        const uint32_t* Aw = reinterpret_cast<const uint32_t*>(As);
        const uint32_t* Bw = reinterpret_cast<const uint32_t*>(Bs);
#pragma unroll
        for (int ks = 0; ks < 4; ks++) {
            const int wb = ks * 8;
            uint32_t a[4][4], b[4][2];
#pragma unroll
            for (int mt = 0; mt < 4; mt++) {
                int r0 = warpRow + mt * 16;
                a[mt][0] = Aw[(r0 + grp    ) * 36 + wb + tig];
                a[mt][1] = Aw[(r0 + grp + 8) * 36 + wb + tig];
                a[mt][2] = Aw[(r0 + grp    ) * 36 + wb + 4 + tig];
                a[mt][3] = Aw[(r0 + grp + 8) * 36 + wb + 4 + tig];
            }
#pragma unroll
            for (int nt = 0; nt < 4; nt++) {
                int cn = warpCol + nt * 8 + grp;
                b[nt][0] = Bw[cn * 36 + wb + tig];
                b[nt][1] = Bw[cn * 36 + wb + 4 + tig];
            }
#pragma unroll
            for (int mt = 0; mt < 4; mt++)
#pragma unroll
                for (int nt = 0; nt < 4; nt++) {
                    asm volatile(
                        "mma.sync.aligned.m16n8k16.row.col.f32.f16.f16.f32 "
                        "{%0,%1,%2,%3}, {%4,%5,%6,%7}, {%8,%9}, {%0,%1,%2,%3};\n"
                        : "+f"(acc[mt][nt][0]), "+f"(acc[mt][nt][1]),
                          "+f"(acc[mt][nt][2]), "+f"(acc[mt][nt][3])
                        : "r"(a[mt][0]), "r"(a[mt][1]), "r"(a[mt][2]), "r"(a[mt][3]),
                          "r"(b[nt][0]), "r"(b[nt][1]));
                }
        }
        __syncthreads();
    }

    // ---- epilogue
#pragma unroll
    for (int nt = 0; nt < 4; nt++) {
        int c = warpCol + nt * 8 + 2 * tig;
        float b0 = bias[c], b1 = bias[c + 1];
#pragma unroll
        for (int mt = 0; mt < 4; mt++) {
            int r = rowBase + warpRow + mt * 16 + grp;
            float v0 = fmaxf(acc[mt][nt][0] + b0, 0.f);
            float v1 = fmaxf(acc[mt][nt][1] + b1, 0.f);
            float v2 = fmaxf(acc[mt][nt][2] + b0, 0.f);
            float v3 = fmaxf(acc[mt][nt][3] + b1, 0.f);
            if (out_to_h1) {
                if (r < NN)
                    *reinterpret_cast<__half2*>(&g_h1h[(size_t)r * D + c]) =
                        __floats2half2_rn(v0, v1);
                if (r + 8 < NN)
                    *reinterpret_cast<__half2*>(&g_h1h[(size_t)(r + 8) * D + c]) =
                        __floats2half2_rn(v2, v3);
            } else {
                if (r < NN)
                    *reinterpret_cast<float2*>(&outbuf[(size_t)r * D + c]) =
                        make_float2(v0, v1);
                if (r + 8 < NN)
                    *reinterpret_cast<float2*>(&outbuf[(size_t)(r + 8) * D + c]) =
                        make_float2(v2, v3);
            }
        }
    }
}

// ---------------------------------------------------------------------------
extern "C" void kernel_launch(void* const* d_in, const int* in_sizes, int n_in,
                              void* d_out, int out_size) {
    const float* x   = (const float*)d_in[0];
    const void*  ei  = d_in[1];
    const float* W1l = (const float*)d_in[2];
    const float* b1  = (const float*)d_in[3];
    const float* W1r = (const float*)d_in[4];
    const float* W2l = (const float*)d_in[5];
    const float* b2  = (const float*)d_in[6];
    const float* W2r = (const float*)d_in[7];
    float*       out = (float*)d_out;

    const int E = in_sizes[1] / 2;
    const int eblocks = (E + 255) / 256;
    const int gemmBlocks = (NN + BM - 1) / BM;
    const int gatherBlocks = (NN + 7) / 8;
    const int initBlocks = (int)(((long long)NN * D / 8 + 255) / 256);

    k_init<<<initBlocks, 256>>>(x, (const int*)ei, in_sizes[1],
                                W1l, W1r, W2l, W2r);

    // CSR build
    k_hist<<<eblocks, 256>>>(ei, E);
    k_scan1<<<SCAN_BLOCKS, 256>>>();
    k_scan3<<<SCAN_BLOCKS, 256>>>(E);
    k_fill<<<eblocks, 256>>>(ei, E);

    // Layer 1
    k_gather<<<gatherBlocks, 256>>>(0);
    k_gemm<<<gemmBlocks, 256>>>(b1, out, 0, 1);   // -> g_h1h (fp16)

    // Layer 2
    k_gather<<<gatherBlocks, 256>>>(1);
    k_gemm<<<gemmBlocks, 256>>>(b2, out, 1, 0);   // -> d_out
}